// round 2
// baseline (speedup 1.0000x reference)
#include <cuda_runtime.h>
#include <math.h>

#define B_ 2
#define H_ 64
#define W_ 64
#define T_ 4096
#define C_ 192
#define NTOT (B_*T_*C_)

// ---------------- scratch (static device memory; no allocation) ----------------
__device__ float g_xk[NTOT];
__device__ float g_xv[NTOT];
__device__ float g_xr[NTOT];
__device__ float g_k [NTOT];
__device__ float g_v [NTOT];
__device__ float g_sr[NTOT];
__device__ float g_kT[NTOT];
__device__ float g_vT[NTOT];
__device__ float g_yT[NTOT];
__device__ float g_ysr[NTOT];
__device__ float g_gb[B_*4*T_];

// ring offsets (PAD=2, RB=1): 16 border cells of the 5x5 neighborhood
__constant__ float c_prfx[16] = {-2,-2,-2,-2, -2,-1,0,1,  2,2,2,2,  -1,0,1,2};
__constant__ float c_prfy[16] = {-2,-1,0,1,   2,2,2,2,  -1,0,1,2,  -2,-2,-2,-2};

// ---------------- prep: q_shift + token mixing ----------------
__global__ void prep_kernel(const float* __restrict__ x,
                            const float* __restrict__ mk,
                            const float* __restrict__ mv,
                            const float* __restrict__ mr) {
    int gt = blockIdx.x;            // b*T + t
    int tt = gt % T_;
    int hh = tt >> 6, ww = tt & 63;
    int c = threadIdx.x;
    size_t ridx = (size_t)gt * C_ + c;
    float xc = x[ridx];
    float xx;
    int g = c / 48;
    if (g == 0)      xx = (ww >= 1)  ? x[ridx - C_]      : 0.f;
    else if (g == 1) xx = (ww <= 62) ? x[ridx + C_]      : 0.f;
    else if (g == 2) xx = (hh >= 1)  ? x[ridx - 64*C_]   : 0.f;
    else             xx = (hh <= 62) ? x[ridx + 64*C_]   : 0.f;
    float a;
    a = mk[c]; g_xk[ridx] = a*xc + (1.f-a)*xx;
    a = mv[c]; g_xv[ridx] = a*xc + (1.f-a)*xx;
    a = mr[c]; g_xr[ridx] = a*xc + (1.f-a)*xx;
}

// ---------------- band estimate: dual 7-tap conv + BN + sigmoid ----------------
__global__ void gb_kernel(const float* __restrict__ x,
                          const float* __restrict__ cvw, const float* __restrict__ cvb,
                          const float* __restrict__ bns_v, const float* __restrict__ bnb_v,
                          const float* __restrict__ chw, const float* __restrict__ chb,
                          const float* __restrict__ bns_h, const float* __restrict__ bnb_h) {
    int gt = blockIdx.x;
    int b = gt / T_; int tt = gt % T_;
    int hh = tt >> 6, ww = tt & 63;
    int c = threadIdx.x;
    const float* xb = x + (size_t)b * T_ * C_;
    float s0 = 0.f, s1 = 0.f, s2 = 0.f, s3 = 0.f;
#pragma unroll
    for (int r = 0; r < 7; r++) {
        int hy = hh + r - 3;
        if (hy >= 0 && hy < H_) {
            float xv = xb[(size_t)(hy*W_ + ww)*C_ + c];
            s0 += xv * cvw[c*7 + r];
            s1 += xv * cvw[(C_ + c)*7 + r];
        }
        int wy = ww + r - 3;
        if (wy >= 0 && wy < W_) {
            float xh = xb[(size_t)(hh*W_ + wy)*C_ + c];
            s2 += xh * chw[c*7 + r];
            s3 += xh * chw[(C_ + c)*7 + r];
        }
    }
#pragma unroll
    for (int off = 16; off; off >>= 1) {
        s0 += __shfl_xor_sync(0xffffffffu, s0, off);
        s1 += __shfl_xor_sync(0xffffffffu, s1, off);
        s2 += __shfl_xor_sync(0xffffffffu, s2, off);
        s3 += __shfl_xor_sync(0xffffffffu, s3, off);
    }
    __shared__ float red[6][4];
    int lane = c & 31, wid = c >> 5;
    if (lane == 0) { red[wid][0]=s0; red[wid][1]=s1; red[wid][2]=s2; red[wid][3]=s3; }
    __syncthreads();
    if (c < 4) {
        int j = c;
        float tot = red[0][j]+red[1][j]+red[2][j]+red[3][j]+red[4][j]+red[5][j];
        const float inv = 1.0f / sqrtf(1.0f + 1e-5f);
        float bias, scale, shift;
        if (j == 0)      { bias = cvb[0]; scale = bns_v[0]; shift = bnb_v[0]; }
        else if (j == 1) { bias = cvb[1]; scale = bns_v[1]; shift = bnb_v[1]; }
        else if (j == 2) { bias = chb[0]; scale = bns_h[0]; shift = bnb_h[0]; }
        else             { bias = chb[1]; scale = bns_h[1]; shift = bnb_h[1]; }
        float val = (tot + bias) * (scale * inv) + shift;
        float sg = 1.f / (1.f + expf(-val));
        g_gb[((size_t)b*4 + j)*T_ + tt] = 2.f * sg;
    }
}

// ---------------- fp32 tiled GEMM: C[M,192] = A[M,192] @ W[192,192] ----------------
__global__ __launch_bounds__(256) void gemm192(const float* __restrict__ A,
                                               const float* __restrict__ Wt,
                                               float* __restrict__ Cout, int sig) {
    __shared__ float As[16][65];
    __shared__ float Bs[16][64];
    int bm = blockIdx.x * 64;
    int bn = blockIdx.y * 64;
    int tid = threadIdx.x;
    int tx = tid & 15, ty = tid >> 4;
    float acc[4][4] = {};
    for (int k0 = 0; k0 < C_; k0 += 16) {
#pragma unroll
        for (int i = 0; i < 4; i++) {
            int e = tid + i*256;
            int m = e >> 4, kk = e & 15;
            As[kk][m] = A[(size_t)(bm+m)*C_ + k0 + kk];
        }
#pragma unroll
        for (int i = 0; i < 4; i++) {
            int e = tid + i*256;
            int kk = e >> 6, n = e & 63;
            Bs[kk][n] = Wt[(size_t)(k0+kk)*C_ + bn + n];
        }
        __syncthreads();
#pragma unroll
        for (int kk = 0; kk < 16; kk++) {
            float ra[4], rb[4];
#pragma unroll
            for (int i = 0; i < 4; i++) ra[i] = As[kk][ty*4+i];
#pragma unroll
            for (int i = 0; i < 4; i++) rb[i] = Bs[kk][tx*4+i];
#pragma unroll
            for (int i = 0; i < 4; i++)
#pragma unroll
                for (int j = 0; j < 4; j++)
                    acc[i][j] = fmaf(ra[i], rb[j], acc[i][j]);
        }
        __syncthreads();
    }
#pragma unroll
    for (int i = 0; i < 4; i++)
#pragma unroll
        for (int j = 0; j < 4; j++) {
            float v = acc[i][j];
            if (sig) v = 1.f / (1.f + expf(-v));
            Cout[(size_t)(bm + ty*4 + i)*C_ + bn + tx*4 + j] = v;
        }
}

// ---------------- adaptive peak: v += x - mean_16(ring gather) ----------------
__global__ void peak_kernel(const float* __restrict__ x) {
    int gt = blockIdx.x;
    int b = gt / T_; int tt = gt % T_;
    int hh = tt >> 6, ww = tt & 63;
    __shared__ int   s_lt[16], s_rb[16];
    __shared__ float s_wlt[16], s_wrb[16];
    int tid = threadIdx.x;
    if (tid < 16) {
        int o = tid;
        int blk = o >> 2;
        const float* gbp = g_gb + (size_t)b*4*T_;
        float mx = 0.f, my = 0.f;
        if (blk == 0)      mx = -gbp[tt];
        else if (blk == 1) my =  gbp[3*T_ + tt];
        else if (blk == 2) mx =  gbp[T_ + tt];
        else               my = -gbp[2*T_ + tt];
        float px = (float)(hh + 2) + c_prfx[o] + mx;
        float py = (float)(ww + 2) + c_prfy[o] + my;
        float flx = floorf(px), fly = floorf(py);
        float qltx = fminf(fmaxf(flx,      0.f), 67.f);
        float qlty = fminf(fmaxf(fly,      0.f), 67.f);
        float qrbx = fminf(fmaxf(flx+1.f,  0.f), 67.f);
        float qrby = fminf(fmaxf(fly+1.f,  0.f), 67.f);
        float pxc  = fminf(fmaxf(px,       0.f), 67.f);
        float pyc  = fminf(fmaxf(py,       0.f), 67.f);
        float glt = (1.f + (qltx - pxc)) * (1.f + (qlty - pyc));
        float grb = (1.f - (qrbx - pxc)) * (1.f - (qrby - pyc));
        int rlt = min(max((int)qltx - 2, 0), 63);
        int clt = min(max((int)qlty - 2, 0), 63);
        int rrb = min(max((int)qrbx - 2, 0), 63);
        int crb = min(max((int)qrby - 2, 0), 63);
        s_lt[o] = rlt*64 + clt;  s_rb[o] = rrb*64 + crb;
        s_wlt[o] = glt;          s_wrb[o] = grb;
    }
    __syncthreads();
    int c = tid;
    const float* xb = x + (size_t)b * T_ * C_;
    float acc = 0.f;
#pragma unroll
    for (int o = 0; o < 16; o++) {
        acc += s_wlt[o] * xb[(size_t)s_lt[o]*C_ + c];
        acc += s_wrb[o] * xb[(size_t)s_rb[o]*C_ + c];
    }
    size_t idx = (size_t)gt * C_ + c;
    g_v[idx] += x[idx] - acc * (1.f/16.f);
}

// ---------------- transpose (B,T,C) -> (B,C,T) ----------------
__global__ void transpose_kernel(const float* __restrict__ in, float* __restrict__ out) {
    __shared__ float tile[32][33];
    int b = blockIdx.z;
    int t0 = blockIdx.x * 32, c0 = blockIdx.y * 32;
    const float* inb = in + (size_t)b * T_ * C_;
    float* outb = out + (size_t)b * C_ * T_;
#pragma unroll
    for (int i = threadIdx.y; i < 32; i += 8)
        tile[i][threadIdx.x] = inb[(size_t)(t0+i)*C_ + c0 + threadIdx.x];
    __syncthreads();
#pragma unroll
    for (int i = threadIdx.y; i < 32; i += 8)
        outb[(size_t)(c0+i)*T_ + t0 + threadIdx.x] = tile[threadIdx.x][i];
}

// ---------------- sr * y^T -> (B,T,C) ----------------
__global__ void mulT_kernel() {
    __shared__ float tile[32][33];
    int b = blockIdx.z;
    int t0 = blockIdx.x * 32, c0 = blockIdx.y * 32;
    const float* yb = g_yT + (size_t)b * C_ * T_;
#pragma unroll
    for (int i = threadIdx.y; i < 32; i += 8)
        tile[threadIdx.x][i] = yb[(size_t)(c0+i)*T_ + t0 + threadIdx.x];
    __syncthreads();
#pragma unroll
    for (int i = threadIdx.y; i < 32; i += 8) {
        size_t idx = ((size_t)b*T_ + t0 + i)*C_ + c0 + threadIdx.x;
        g_ysr[idx] = g_sr[idx] * tile[i][threadIdx.x];
    }
}

// ---------------- bidirectional WKV scan (fused, unstabilized fp32) ----------------
struct Agg { float a, b, dl; };
__device__ __forceinline__ Agg combine(Agg p, Agg s) {
    Agg r;
    r.a  = fmaf(s.dl, p.a, s.a);
    r.b  = fmaf(s.dl, p.b, s.b);
    r.dl = p.dl * s.dl;
    return r;
}

__device__ __forceinline__ Agg shfl_up_agg(Agg v, int off) {
    Agg r;
    r.a  = __shfl_up_sync(0xffffffffu, v.a,  off);
    r.b  = __shfl_up_sync(0xffffffffu, v.b,  off);
    r.dl = __shfl_up_sync(0xffffffffu, v.dl, off);
    return r;
}
__device__ __forceinline__ Agg shfl_dn_agg(Agg v, int off) {
    Agg r;
    r.a  = __shfl_down_sync(0xffffffffu, v.a,  off);
    r.b  = __shfl_down_sync(0xffffffffu, v.b,  off);
    r.dl = __shfl_down_sync(0xffffffffu, v.dl, off);
    return r;
}

__global__ __launch_bounds__(256) void wkv_kernel(const float* __restrict__ sd,
                                                  const float* __restrict__ sf) {
    __shared__ Agg warpAgg[8];
    __shared__ Agg warpPre[8];
    int bc = blockIdx.x;             // b*C + c
    int c = bc % C_;
    float w  = sd[c] * (1.0f / T_);
    float u  = sf[c] * (1.0f / T_);
    float d  = expf(-w);
    float eu = expf(u);
    float d2 = d*d, d4 = d2*d2, d8 = d4*d4, d16 = d8*d8;
    int tid = threadIdx.x;
    int lane = tid & 31, wid = tid >> 5;
    const float* kp = g_kT + (size_t)bc * T_;
    const float* vp = g_vT + (size_t)bc * T_;
    float* yp = g_yT + (size_t)bc * T_;
    int t0 = tid * 16;

    float ek[16], vv[16];
#pragma unroll
    for (int i = 0; i < 16; i++) {
        ek[i] = expf(kp[t0 + i]);
        vv[i] = vp[t0 + i];
    }

    // ---- forward ----
    Agg ag; ag.a = 0.f; ag.b = 0.f; ag.dl = d16;
#pragma unroll
    for (int i = 0; i < 16; i++) {
        ag.a = fmaf(d, ag.a, ek[i]);
        ag.b = fmaf(d, ag.b, ek[i]*vv[i]);
    }
    // inclusive warp scan
    Agg inc = ag;
#pragma unroll
    for (int off = 1; off < 32; off <<= 1) {
        Agg o = shfl_up_agg(inc, off);
        if (lane >= off) inc = combine(o, inc);
    }
    if (lane == 31) warpAgg[wid] = inc;
    __syncthreads();
    if (tid == 0) {
        Agg run; run.a = 0.f; run.b = 0.f; run.dl = 1.f;
        for (int i = 0; i < 8; i++) { warpPre[i] = run; run = combine(run, warpAgg[i]); }
    }
    __syncthreads();
    Agg pl = shfl_up_agg(inc, 1);
    Agg ex = warpPre[wid];
    if (lane > 0) ex = combine(ex, pl);

    float af = ex.a, bf = ex.b;
    float saf[16], sbf[16];
#pragma unroll
    for (int i = 0; i < 16; i++) {
        saf[i] = af; sbf[i] = bf;
        af = fmaf(d, af, ek[i]);
        bf = fmaf(d, bf, ek[i]*vv[i]);
    }
    __syncthreads();   // protect warpPre/warpAgg reuse

    // ---- backward ----
    Agg bg; bg.a = 0.f; bg.b = 0.f; bg.dl = d16;
#pragma unroll
    for (int i = 15; i >= 0; i--) {
        bg.a = fmaf(d, bg.a, ek[i]);
        bg.b = fmaf(d, bg.b, ek[i]*vv[i]);
    }
    Agg binc = bg;
#pragma unroll
    for (int off = 1; off < 32; off <<= 1) {
        Agg o = shfl_dn_agg(binc, off);
        if (lane < 32 - off) binc = combine(o, binc);
    }
    if (lane == 0) warpAgg[wid] = binc;
    __syncthreads();
    if (tid == 0) {
        Agg run; run.a = 0.f; run.b = 0.f; run.dl = 1.f;
        for (int i = 7; i >= 0; i--) { warpPre[i] = run; run = combine(run, warpAgg[i]); }
    }
    __syncthreads();
    Agg bpl = shfl_dn_agg(binc, 1);
    Agg bex = warpPre[wid];
    if (lane < 31) bex = combine(bex, bpl);

    float ab = bex.a, bb = bex.b;
#pragma unroll
    for (int i = 15; i >= 0; i--) {
        float es  = eu * ek[i];
        float num = sbf[i] + bb + es * vv[i];
        float den = saf[i] + ab + es;
        yp[t0 + i] = num / den;
        ab = fmaf(d, ab, ek[i]);
        bb = fmaf(d, bb, ek[i]*vv[i]);
    }
}

// ---------------- launch ----------------
static float* sym_addr(const void* sym) {
    void* p = nullptr;
    cudaGetSymbolAddress(&p, sym);
    return (float*)p;
}

extern "C" void kernel_launch(void* const* d_in, const int* in_sizes, int n_in,
                              void* d_out, int out_size) {
    const float* x = (const float*)d_in[0];
    int base = (in_sizes[1] == 1) ? 3 : 1;   // skip h, w scalars if present
    const float* mk    = (const float*)d_in[base + 0];
    const float* mv    = (const float*)d_in[base + 1];
    const float* mr    = (const float*)d_in[base + 2];
    const float* Wk    = (const float*)d_in[base + 3];
    const float* Wv    = (const float*)d_in[base + 4];
    const float* Wr    = (const float*)d_in[base + 5];
    const float* Wo    = (const float*)d_in[base + 6];
    const float* sd    = (const float*)d_in[base + 7];
    const float* sf    = (const float*)d_in[base + 8];
    const float* cvw   = (const float*)d_in[base + 9];
    const float* cvb   = (const float*)d_in[base + 10];
    const float* bns_v = (const float*)d_in[base + 11];
    const float* bnb_v = (const float*)d_in[base + 12];
    const float* chw   = (const float*)d_in[base + 13];
    const float* chb   = (const float*)d_in[base + 14];
    const float* bns_h = (const float*)d_in[base + 15];
    const float* bnb_h = (const float*)d_in[base + 16];

    float* p_xk  = sym_addr(g_xk);
    float* p_xv  = sym_addr(g_xv);
    float* p_xr  = sym_addr(g_xr);
    float* p_k   = sym_addr(g_k);
    float* p_v   = sym_addr(g_v);
    float* p_sr  = sym_addr(g_sr);
    float* p_kT  = sym_addr(g_kT);
    float* p_vT  = sym_addr(g_vT);
    float* p_ysr = sym_addr(g_ysr);

    dim3 gemm_grid(128, 3);
    dim3 tr_grid(T_/32, C_/32, B_);
    dim3 tr_blk(32, 8);

    prep_kernel<<<B_*T_, C_>>>(x, mk, mv, mr);
    gb_kernel<<<B_*T_, C_>>>(x, cvw, cvb, bns_v, bnb_v, chw, chb, bns_h, bnb_h);
    gemm192<<<gemm_grid, 256>>>(p_xk, Wk, p_k, 0);
    gemm192<<<gemm_grid, 256>>>(p_xv, Wv, p_v, 0);
    gemm192<<<gemm_grid, 256>>>(p_xr, Wr, p_sr, 1);
    peak_kernel<<<B_*T_, C_>>>(x);
    transpose_kernel<<<tr_grid, tr_blk>>>(p_k, p_kT);
    transpose_kernel<<<tr_grid, tr_blk>>>(p_v, p_vT);
    wkv_kernel<<<B_*C_, 256>>>(sd, sf);
    mulT_kernel<<<tr_grid, tr_blk>>>();
    gemm192<<<gemm_grid, 256>>>(p_ysr, Wo, (float*)d_out, 0);
}

// round 3
// speedup vs baseline: 1.5075x; 1.5075x over previous
#include <cuda_runtime.h>
#include <math.h>

#define B_ 2
#define H_ 64
#define W_ 64
#define T_ 4096
#define C_ 192
#define NTOT (B_*T_*C_)

// ---------------- scratch (static device memory; no allocation) ----------------
__device__ float g_xk[NTOT];
__device__ float g_xv[NTOT];
__device__ float g_xr[NTOT];
__device__ float g_k [NTOT];
__device__ float g_v [NTOT];
__device__ float g_sr[NTOT];
__device__ float g_kT[NTOT];
__device__ float g_vT[NTOT];
__device__ float g_yT[NTOT];
__device__ float g_ysr[NTOT];
__device__ float g_gb[B_*4*T_];

// ring offsets (PAD=2, RB=1): 16 border cells of the 5x5 neighborhood
__constant__ float c_prfx[16] = {-2,-2,-2,-2, -2,-1,0,1,  2,2,2,2,  -1,0,1,2};
__constant__ float c_prfy[16] = {-2,-1,0,1,   2,2,2,2,  -1,0,1,2,  -2,-2,-2,-2};

// ---------------- prep: q_shift + token mixing ----------------
__global__ void prep_kernel(const float* __restrict__ x,
                            const float* __restrict__ mk,
                            const float* __restrict__ mv,
                            const float* __restrict__ mr) {
    int gt = blockIdx.x;            // b*T + t
    int tt = gt % T_;
    int hh = tt >> 6, ww = tt & 63;
    int c = threadIdx.x;
    size_t ridx = (size_t)gt * C_ + c;
    float xc = x[ridx];
    float xx;
    int g = c / 48;
    if (g == 0)      xx = (ww >= 1)  ? x[ridx - C_]      : 0.f;
    else if (g == 1) xx = (ww <= 62) ? x[ridx + C_]      : 0.f;
    else if (g == 2) xx = (hh >= 1)  ? x[ridx - 64*C_]   : 0.f;
    else             xx = (hh <= 62) ? x[ridx + 64*C_]   : 0.f;
    float a;
    a = mk[c]; g_xk[ridx] = a*xc + (1.f-a)*xx;
    a = mv[c]; g_xv[ridx] = a*xc + (1.f-a)*xx;
    a = mr[c]; g_xr[ridx] = a*xc + (1.f-a)*xx;
}

// ---------------- band estimate: dual 7-tap conv + BN + sigmoid ----------------
__global__ void gb_kernel(const float* __restrict__ x,
                          const float* __restrict__ cvw, const float* __restrict__ cvb,
                          const float* __restrict__ bns_v, const float* __restrict__ bnb_v,
                          const float* __restrict__ chw, const float* __restrict__ chb,
                          const float* __restrict__ bns_h, const float* __restrict__ bnb_h) {
    int gt = blockIdx.x;
    int b = gt / T_; int tt = gt % T_;
    int hh = tt >> 6, ww = tt & 63;
    int c = threadIdx.x;
    const float* xb = x + (size_t)b * T_ * C_;
    float s0 = 0.f, s1 = 0.f, s2 = 0.f, s3 = 0.f;
#pragma unroll
    for (int r = 0; r < 7; r++) {
        int hy = hh + r - 3;
        if (hy >= 0 && hy < H_) {
            float xv = xb[(size_t)(hy*W_ + ww)*C_ + c];
            s0 += xv * cvw[c*7 + r];
            s1 += xv * cvw[(C_ + c)*7 + r];
        }
        int wy = ww + r - 3;
        if (wy >= 0 && wy < W_) {
            float xh = xb[(size_t)(hh*W_ + wy)*C_ + c];
            s2 += xh * chw[c*7 + r];
            s3 += xh * chw[(C_ + c)*7 + r];
        }
    }
#pragma unroll
    for (int off = 16; off; off >>= 1) {
        s0 += __shfl_xor_sync(0xffffffffu, s0, off);
        s1 += __shfl_xor_sync(0xffffffffu, s1, off);
        s2 += __shfl_xor_sync(0xffffffffu, s2, off);
        s3 += __shfl_xor_sync(0xffffffffu, s3, off);
    }
    __shared__ float red[6][4];
    int lane = c & 31, wid = c >> 5;
    if (lane == 0) { red[wid][0]=s0; red[wid][1]=s1; red[wid][2]=s2; red[wid][3]=s3; }
    __syncthreads();
    if (c < 4) {
        int j = c;
        float tot = red[0][j]+red[1][j]+red[2][j]+red[3][j]+red[4][j]+red[5][j];
        const float inv = 1.0f / sqrtf(1.0f + 1e-5f);
        float bias, scale, shift;
        if (j == 0)      { bias = cvb[0]; scale = bns_v[0]; shift = bnb_v[0]; }
        else if (j == 1) { bias = cvb[1]; scale = bns_v[1]; shift = bnb_v[1]; }
        else if (j == 2) { bias = chb[0]; scale = bns_h[0]; shift = bnb_h[0]; }
        else             { bias = chb[1]; scale = bns_h[1]; shift = bnb_h[1]; }
        float val = (tot + bias) * (scale * inv) + shift;
        float sg = 1.f / (1.f + expf(-val));
        g_gb[((size_t)b*4 + j)*T_ + tt] = 2.f * sg;
    }
}

// ---------------- tf32 tensor-core GEMM: C[M,192] = A[M,192] @ W[192,192] ----------------
// block tile 64x64, 4 warps (2x2), warp tile 32x32 (2x4 m16n8k8 mmas / k-step)
#define AS_STRIDE 36
#define BS_STRIDE 68

__device__ __forceinline__ unsigned f2tf32(float x) {
    unsigned r;
    asm("cvt.rna.tf32.f32 %0, %1;" : "=r"(r) : "f"(x));
    return r;
}

__global__ __launch_bounds__(128) void gemm192_tc(const float* __restrict__ A,
                                                  const float* __restrict__ Wt,
                                                  float* __restrict__ Cout, int sig) {
    __shared__ unsigned As[2][64 * AS_STRIDE];   // [m][k], tf32 bits
    __shared__ unsigned Bs[2][32 * BS_STRIDE];   // [k][n], tf32 bits

    int tid  = threadIdx.x;
    int warp = tid >> 5, lane = tid & 31;
    int bm = blockIdx.x * 64;
    int bn = blockIdx.y * 64;
    int wm = (warp >> 1) * 32;
    int wn = (warp & 1) * 32;
    int gid = lane >> 2;     // group id 0..7
    int tig = lane & 3;      // thread in group 0..3

    // load mapping
    int ar = tid >> 3;            // 0..15 (rows ar, ar+16, ar+32, ar+48)
    int ac = (tid & 7) * 4;       // k offset within 32
    int br = tid >> 4;            // 0..7 (k rows br, br+8, br+16, br+24)
    int bc = (tid & 15) * 4;      // n offset within 64

    float acc[2][4][4];
#pragma unroll
    for (int i = 0; i < 2; i++)
#pragma unroll
        for (int j = 0; j < 4; j++)
#pragma unroll
            for (int r = 0; r < 4; r++) acc[i][j][r] = 0.f;

    float4 pa[4], pb[4];
    // prefetch chunk 0
#pragma unroll
    for (int i = 0; i < 4; i++)
        pa[i] = *(const float4*)&A[(size_t)(bm + ar + i*16)*C_ + ac];
#pragma unroll
    for (int i = 0; i < 4; i++)
        pb[i] = *(const float4*)&Wt[(size_t)(br + i*8)*C_ + bn + bc];

    // store chunk 0
#pragma unroll
    for (int i = 0; i < 4; i++) {
        unsigned* p = &As[0][(ar + i*16)*AS_STRIDE + ac];
        p[0]=f2tf32(pa[i].x); p[1]=f2tf32(pa[i].y); p[2]=f2tf32(pa[i].z); p[3]=f2tf32(pa[i].w);
    }
#pragma unroll
    for (int i = 0; i < 4; i++) {
        unsigned* p = &Bs[0][(br + i*8)*BS_STRIDE + bc];
        p[0]=f2tf32(pb[i].x); p[1]=f2tf32(pb[i].y); p[2]=f2tf32(pb[i].z); p[3]=f2tf32(pb[i].w);
    }
    __syncthreads();

    for (int kc = 0; kc < 6; kc++) {
        int cur = kc & 1;
        if (kc < 5) {
            int k0 = (kc + 1) * 32;
#pragma unroll
            for (int i = 0; i < 4; i++)
                pa[i] = *(const float4*)&A[(size_t)(bm + ar + i*16)*C_ + k0 + ac];
#pragma unroll
            for (int i = 0; i < 4; i++)
                pb[i] = *(const float4*)&Wt[(size_t)(k0 + br + i*8)*C_ + bn + bc];
        }
        const unsigned* as = As[cur];
        const unsigned* bs = Bs[cur];
#pragma unroll
        for (int ks = 0; ks < 4; ks++) {
            int kk0 = ks * 8;
            unsigned afr[2][4], bfr[4][2];
#pragma unroll
            for (int mi = 0; mi < 2; mi++) {
                int rbase = (wm + mi*16 + gid) * AS_STRIDE;
                afr[mi][0] = as[rbase + kk0 + tig];
                afr[mi][1] = as[rbase + 8*AS_STRIDE + kk0 + tig];
                afr[mi][2] = as[rbase + kk0 + tig + 4];
                afr[mi][3] = as[rbase + 8*AS_STRIDE + kk0 + tig + 4];
            }
#pragma unroll
            for (int ni = 0; ni < 4; ni++) {
                int col = wn + ni*8 + gid;
                bfr[ni][0] = bs[(kk0 + tig)*BS_STRIDE + col];
                bfr[ni][1] = bs[(kk0 + tig + 4)*BS_STRIDE + col];
            }
#pragma unroll
            for (int mi = 0; mi < 2; mi++)
#pragma unroll
                for (int ni = 0; ni < 4; ni++) {
                    float* d = acc[mi][ni];
                    asm volatile(
                        "mma.sync.aligned.m16n8k8.row.col.f32.tf32.tf32.f32 "
                        "{%0,%1,%2,%3}, {%4,%5,%6,%7}, {%8,%9}, {%0,%1,%2,%3};\n"
                        : "+f"(d[0]), "+f"(d[1]), "+f"(d[2]), "+f"(d[3])
                        : "r"(afr[mi][0]), "r"(afr[mi][1]), "r"(afr[mi][2]), "r"(afr[mi][3]),
                          "r"(bfr[ni][0]), "r"(bfr[ni][1]));
                }
        }
        if (kc < 5) {
            __syncthreads();
            int nxt = cur ^ 1;
#pragma unroll
            for (int i = 0; i < 4; i++) {
                unsigned* p = &As[nxt][(ar + i*16)*AS_STRIDE + ac];
                p[0]=f2tf32(pa[i].x); p[1]=f2tf32(pa[i].y); p[2]=f2tf32(pa[i].z); p[3]=f2tf32(pa[i].w);
            }
#pragma unroll
            for (int i = 0; i < 4; i++) {
                unsigned* p = &Bs[nxt][(br + i*8)*BS_STRIDE + bc];
                p[0]=f2tf32(pb[i].x); p[1]=f2tf32(pb[i].y); p[2]=f2tf32(pb[i].z); p[3]=f2tf32(pb[i].w);
            }
            __syncthreads();
        }
    }

    // epilogue
#pragma unroll
    for (int mi = 0; mi < 2; mi++) {
        int r0 = bm + wm + mi*16 + gid;
#pragma unroll
        for (int ni = 0; ni < 4; ni++) {
            int c0 = bn + wn + ni*8 + tig*2;
            float v0 = acc[mi][ni][0], v1 = acc[mi][ni][1];
            float v2 = acc[mi][ni][2], v3 = acc[mi][ni][3];
            if (sig) {
                v0 = 1.f/(1.f+expf(-v0)); v1 = 1.f/(1.f+expf(-v1));
                v2 = 1.f/(1.f+expf(-v2)); v3 = 1.f/(1.f+expf(-v3));
            }
            *(float2*)&Cout[(size_t)r0*C_ + c0]     = make_float2(v0, v1);
            *(float2*)&Cout[(size_t)(r0+8)*C_ + c0] = make_float2(v2, v3);
        }
    }
}

// ---------------- adaptive peak: v += x - mean_16(ring gather) ----------------
__global__ void peak_kernel(const float* __restrict__ x) {
    int gt = blockIdx.x;
    int b = gt / T_; int tt = gt % T_;
    int hh = tt >> 6, ww = tt & 63;
    __shared__ int   s_lt[16], s_rb[16];
    __shared__ float s_wlt[16], s_wrb[16];
    int tid = threadIdx.x;
    if (tid < 16) {
        int o = tid;
        int blk = o >> 2;
        const float* gbp = g_gb + (size_t)b*4*T_;
        float mx = 0.f, my = 0.f;
        if (blk == 0)      mx = -gbp[tt];
        else if (blk == 1) my =  gbp[3*T_ + tt];
        else if (blk == 2) mx =  gbp[T_ + tt];
        else               my = -gbp[2*T_ + tt];
        float px = (float)(hh + 2) + c_prfx[o] + mx;
        float py = (float)(ww + 2) + c_prfy[o] + my;
        float flx = floorf(px), fly = floorf(py);
        float qltx = fminf(fmaxf(flx,      0.f), 67.f);
        float qlty = fminf(fmaxf(fly,      0.f), 67.f);
        float qrbx = fminf(fmaxf(flx+1.f,  0.f), 67.f);
        float qrby = fminf(fmaxf(fly+1.f,  0.f), 67.f);
        float pxc  = fminf(fmaxf(px,       0.f), 67.f);
        float pyc  = fminf(fmaxf(py,       0.f), 67.f);
        float glt = (1.f + (qltx - pxc)) * (1.f + (qlty - pyc));
        float grb = (1.f - (qrbx - pxc)) * (1.f - (qrby - pyc));
        int rlt = min(max((int)qltx - 2, 0), 63);
        int clt = min(max((int)qlty - 2, 0), 63);
        int rrb = min(max((int)qrbx - 2, 0), 63);
        int crb = min(max((int)qrby - 2, 0), 63);
        s_lt[o] = rlt*64 + clt;  s_rb[o] = rrb*64 + crb;
        s_wlt[o] = glt;          s_wrb[o] = grb;
    }
    __syncthreads();
    int c = tid;
    const float* xb = x + (size_t)b * T_ * C_;
    float acc = 0.f;
#pragma unroll
    for (int o = 0; o < 16; o++) {
        acc += s_wlt[o] * xb[(size_t)s_lt[o]*C_ + c];
        acc += s_wrb[o] * xb[(size_t)s_rb[o]*C_ + c];
    }
    size_t idx = (size_t)gt * C_ + c;
    g_v[idx] += x[idx] - acc * (1.f/16.f);
}

// ---------------- transpose (B,T,C) -> (B,C,T) ----------------
__global__ void transpose_kernel(const float* __restrict__ in, float* __restrict__ out) {
    __shared__ float tile[32][33];
    int b = blockIdx.z;
    int t0 = blockIdx.x * 32, c0 = blockIdx.y * 32;
    const float* inb = in + (size_t)b * T_ * C_;
    float* outb = out + (size_t)b * C_ * T_;
#pragma unroll
    for (int i = threadIdx.y; i < 32; i += 8)
        tile[i][threadIdx.x] = inb[(size_t)(t0+i)*C_ + c0 + threadIdx.x];
    __syncthreads();
#pragma unroll
    for (int i = threadIdx.y; i < 32; i += 8)
        outb[(size_t)(c0+i)*T_ + t0 + threadIdx.x] = tile[threadIdx.x][i];
}

// ---------------- sr * y^T -> (B,T,C) ----------------
__global__ void mulT_kernel() {
    __shared__ float tile[32][33];
    int b = blockIdx.z;
    int t0 = blockIdx.x * 32, c0 = blockIdx.y * 32;
    const float* yb = g_yT + (size_t)b * C_ * T_;
#pragma unroll
    for (int i = threadIdx.y; i < 32; i += 8)
        tile[threadIdx.x][i] = yb[(size_t)(c0+i)*T_ + t0 + threadIdx.x];
    __syncthreads();
#pragma unroll
    for (int i = threadIdx.y; i < 32; i += 8) {
        size_t idx = ((size_t)b*T_ + t0 + i)*C_ + c0 + threadIdx.x;
        g_ysr[idx] = g_sr[idx] * tile[i][threadIdx.x];
    }
}

// ---------------- bidirectional WKV scan (fused, unstabilized fp32) ----------------
struct Agg { float a, b, dl; };
__device__ __forceinline__ Agg combine(Agg p, Agg s) {
    Agg r;
    r.a  = fmaf(s.dl, p.a, s.a);
    r.b  = fmaf(s.dl, p.b, s.b);
    r.dl = p.dl * s.dl;
    return r;
}

__device__ __forceinline__ Agg shfl_up_agg(Agg v, int off) {
    Agg r;
    r.a  = __shfl_up_sync(0xffffffffu, v.a,  off);
    r.b  = __shfl_up_sync(0xffffffffu, v.b,  off);
    r.dl = __shfl_up_sync(0xffffffffu, v.dl, off);
    return r;
}
__device__ __forceinline__ Agg shfl_dn_agg(Agg v, int off) {
    Agg r;
    r.a  = __shfl_down_sync(0xffffffffu, v.a,  off);
    r.b  = __shfl_down_sync(0xffffffffu, v.b,  off);
    r.dl = __shfl_down_sync(0xffffffffu, v.dl, off);
    return r;
}

__global__ __launch_bounds__(256) void wkv_kernel(const float* __restrict__ sd,
                                                  const float* __restrict__ sf) {
    __shared__ Agg warpAgg[8];
    __shared__ Agg warpPre[8];
    int bc = blockIdx.x;             // b*C + c
    int c = bc % C_;
    float w  = sd[c] * (1.0f / T_);
    float u  = sf[c] * (1.0f / T_);
    float d  = expf(-w);
    float eu = expf(u);
    float d2 = d*d, d4 = d2*d2, d8 = d4*d4, d16 = d8*d8;
    int tid = threadIdx.x;
    int lane = tid & 31, wid = tid >> 5;
    const float* kp = g_kT + (size_t)bc * T_;
    const float* vp = g_vT + (size_t)bc * T_;
    float* yp = g_yT + (size_t)bc * T_;
    int t0 = tid * 16;

    float ek[16], vv[16];
#pragma unroll
    for (int i = 0; i < 16; i++) {
        ek[i] = expf(kp[t0 + i]);
        vv[i] = vp[t0 + i];
    }

    // ---- forward ----
    Agg ag; ag.a = 0.f; ag.b = 0.f; ag.dl = d16;
#pragma unroll
    for (int i = 0; i < 16; i++) {
        ag.a = fmaf(d, ag.a, ek[i]);
        ag.b = fmaf(d, ag.b, ek[i]*vv[i]);
    }
    Agg inc = ag;
#pragma unroll
    for (int off = 1; off < 32; off <<= 1) {
        Agg o = shfl_up_agg(inc, off);
        if (lane >= off) inc = combine(o, inc);
    }
    if (lane == 31) warpAgg[wid] = inc;
    __syncthreads();
    if (tid == 0) {
        Agg run; run.a = 0.f; run.b = 0.f; run.dl = 1.f;
        for (int i = 0; i < 8; i++) { warpPre[i] = run; run = combine(run, warpAgg[i]); }
    }
    __syncthreads();
    Agg pl = shfl_up_agg(inc, 1);
    Agg ex = warpPre[wid];
    if (lane > 0) ex = combine(ex, pl);

    float af = ex.a, bf = ex.b;
    float saf[16], sbf[16];
#pragma unroll
    for (int i = 0; i < 16; i++) {
        saf[i] = af; sbf[i] = bf;
        af = fmaf(d, af, ek[i]);
        bf = fmaf(d, bf, ek[i]*vv[i]);
    }
    __syncthreads();   // protect warpPre/warpAgg reuse

    // ---- backward ----
    Agg bg; bg.a = 0.f; bg.b = 0.f; bg.dl = d16;
#pragma unroll
    for (int i = 15; i >= 0; i--) {
        bg.a = fmaf(d, bg.a, ek[i]);
        bg.b = fmaf(d, bg.b, ek[i]*vv[i]);
    }
    Agg binc = bg;
#pragma unroll
    for (int off = 1; off < 32; off <<= 1) {
        Agg o = shfl_dn_agg(binc, off);
        if (lane < 32 - off) binc = combine(o, binc);
    }
    if (lane == 0) warpAgg[wid] = binc;
    __syncthreads();
    if (tid == 0) {
        Agg run; run.a = 0.f; run.b = 0.f; run.dl = 1.f;
        for (int i = 7; i >= 0; i--) { warpPre[i] = run; run = combine(run, warpAgg[i]); }
    }
    __syncthreads();
    Agg bpl = shfl_dn_agg(binc, 1);
    Agg bex = warpPre[wid];
    if (lane < 31) bex = combine(bex, bpl);

    float ab = bex.a, bb = bex.b;
#pragma unroll
    for (int i = 15; i >= 0; i--) {
        float es  = eu * ek[i];
        float num = sbf[i] + bb + es * vv[i];
        float den = saf[i] + ab + es;
        yp[t0 + i] = num / den;
        ab = fmaf(d, ab, ek[i]);
        bb = fmaf(d, bb, ek[i]*vv[i]);
    }
}

// ---------------- launch ----------------
static float* sym_addr(const void* sym) {
    void* p = nullptr;
    cudaGetSymbolAddress(&p, sym);
    return (float*)p;
}

extern "C" void kernel_launch(void* const* d_in, const int* in_sizes, int n_in,
                              void* d_out, int out_size) {
    const float* x = (const float*)d_in[0];
    int base = (in_sizes[1] == 1) ? 3 : 1;   // skip h, w scalars if present
    const float* mk    = (const float*)d_in[base + 0];
    const float* mv    = (const float*)d_in[base + 1];
    const float* mr    = (const float*)d_in[base + 2];
    const float* Wk    = (const float*)d_in[base + 3];
    const float* Wv    = (const float*)d_in[base + 4];
    const float* Wr    = (const float*)d_in[base + 5];
    const float* Wo    = (const float*)d_in[base + 6];
    const float* sd    = (const float*)d_in[base + 7];
    const float* sf    = (const float*)d_in[base + 8];
    const float* cvw   = (const float*)d_in[base + 9];
    const float* cvb   = (const float*)d_in[base + 10];
    const float* bns_v = (const float*)d_in[base + 11];
    const float* bnb_v = (const float*)d_in[base + 12];
    const float* chw   = (const float*)d_in[base + 13];
    const float* chb   = (const float*)d_in[base + 14];
    const float* bns_h = (const float*)d_in[base + 15];
    const float* bnb_h = (const float*)d_in[base + 16];

    float* p_xk  = sym_addr(g_xk);
    float* p_xv  = sym_addr(g_xv);
    float* p_xr  = sym_addr(g_xr);
    float* p_k   = sym_addr(g_k);
    float* p_v   = sym_addr(g_v);
    float* p_sr  = sym_addr(g_sr);
    float* p_kT  = sym_addr(g_kT);
    float* p_vT  = sym_addr(g_vT);
    float* p_ysr = sym_addr(g_ysr);

    dim3 gemm_grid(128, 3);       // 8192/64 x 192/64
    dim3 tr_grid(T_/32, C_/32, B_);
    dim3 tr_blk(32, 8);

    prep_kernel<<<B_*T_, C_>>>(x, mk, mv, mr);
    gb_kernel<<<B_*T_, C_>>>(x, cvw, cvb, bns_v, bnb_v, chw, chb, bns_h, bnb_h);
    gemm192_tc<<<gemm_grid, 128>>>(p_xk, Wk, p_k, 0);
    gemm192_tc<<<gemm_grid, 128>>>(p_xv, Wv, p_v, 0);
    gemm192_tc<<<gemm_grid, 128>>>(p_xr, Wr, p_sr, 1);
    peak_kernel<<<B_*T_, C_>>>(x);
    transpose_kernel<<<tr_grid, tr_blk>>>(p_k, p_kT);
    transpose_kernel<<<tr_grid, tr_blk>>>(p_v, p_vT);
    wkv_kernel<<<B_*C_, 256>>>(sd, sf);
    mulT_kernel<<<tr_grid, tr_blk>>>();
    gemm192_tc<<<gemm_grid, 128>>>(p_ysr, Wo, (float*)d_out, 0);
}